// round 2
// baseline (speedup 1.0000x reference)
#include <cuda_runtime.h>
#include <cuda_bf16.h>

// VectorQuantizer forward:
//   q      = codebook[categories]   (row gather, 512x768 codebook -> L2 resident)
//   out    = q                       (quantized_st value == q)
//   loss   = 1.25 * mean((q - inputs)^2)
//
// inputs:     [65536, 768] f32
// categories: [65536]      int32 (JAX x64-disabled downcasts the requested int64)
// codebook:   [512, 768]   f32
// out:        65536*768 f32 quantized_st, followed by 1 f32 loss (if out_size permits)

#define VQ_BS 65536
#define VQ_D  768
#define VQ_D4 192   // float4s per row

// Deterministic per-row partial sums (no atomics, graph-safe, allocation-free).
__device__ float g_vq_partials[VQ_BS];

__global__ __launch_bounds__(VQ_D4) void vq_main_kernel(
    const float4* __restrict__ in,
    const int* __restrict__ cat,
    const float4* __restrict__ cb,
    float4* __restrict__ out)
{
    const int row = blockIdx.x;
    const int t   = threadIdx.x;              // 0..191

    // NE = 512 (power of two): mask is a no-op on valid indices but
    // guarantees no OOB gather even if the dtype interpretation is wrong.
    const int c = cat[row] & 511;

    const size_t in_base = (size_t)row * VQ_D4;
    const size_t cb_base = (size_t)c   * VQ_D4;

    float4 a = in[in_base + t];
    float4 q = cb[cb_base + t];

    out[in_base + t] = q;

    float dx = q.x - a.x;
    float dy = q.y - a.y;
    float dz = q.z - a.z;
    float dw = q.w - a.w;
    float s = dx*dx + dy*dy + dz*dz + dw*dw;

    // warp reduction (6 warps of 32)
    #pragma unroll
    for (int o = 16; o > 0; o >>= 1)
        s += __shfl_down_sync(0xffffffffu, s, o);

    __shared__ float ws[6];
    if ((t & 31) == 0) ws[t >> 5] = s;
    __syncthreads();

    if (t == 0) {
        float tot = ws[0] + ws[1] + ws[2] + ws[3] + ws[4] + ws[5];
        g_vq_partials[row] = tot;
    }
}

__global__ __launch_bounds__(1024) void vq_finalize_kernel(float* __restrict__ out,
                                                           int write_loss)
{
    const int t = threadIdx.x;
    float s = 0.0f;
    // 65536 / 1024 = 64 values per thread, deterministic order
    #pragma unroll
    for (int i = 0; i < VQ_BS / 1024; i++)
        s += g_vq_partials[t + i * 1024];

    #pragma unroll
    for (int o = 16; o > 0; o >>= 1)
        s += __shfl_down_sync(0xffffffffu, s, o);

    __shared__ float ws[32];
    if ((t & 31) == 0) ws[t >> 5] = s;
    __syncthreads();

    if (t < 32) {
        float v = ws[t];
        #pragma unroll
        for (int o = 16; o > 0; o >>= 1)
            v += __shfl_down_sync(0xffffffffu, v, o);
        if (t == 0 && write_loss) {
            const double inv_n = 1.0 / ((double)VQ_BS * (double)VQ_D);
            // loss = (CODEBOOK_COST + COMMITMENT_COST) * mse = 1.25 * mse
            out[(size_t)VQ_BS * VQ_D] = (float)(1.25 * (double)v * inv_n);
        }
    }
}

extern "C" void kernel_launch(void* const* d_in, const int* in_sizes, int n_in,
                              void* d_out, int out_size)
{
    const float4* in  = (const float4*)d_in[0];
    const int*    cat = (const int*)d_in[1];
    const float4* cb  = (const float4*)d_in[2];
    float*        out = (float*)d_out;

    vq_main_kernel<<<VQ_BS, VQ_D4>>>(in, cat, cb, (float4*)out);

    const int write_loss = (out_size > VQ_BS * VQ_D) ? 1 : 0;
    vq_finalize_kernel<<<1, 1024>>>(out, write_loss);
}

// round 3
// speedup vs baseline: 1.2293x; 1.2293x over previous
#include <cuda_runtime.h>
#include <cuda_bf16.h>

// VectorQuantizer forward:
//   q    = codebook[categories]   (row gather, 512x768 codebook -> L2 resident)
//   out  = q                       (quantized_st value == q)
//   loss = 1.25 * mean((q - inputs)^2)
//
// inputs:     [65536, 768] f32
// categories: [65536]      int32 (JAX x64-disabled stores int32)
// codebook:   [512, 768]   f32
// out:        65536*768 f32 quantized_st, then 1 f32 loss (if out_size permits)

#define VQ_BS   65536
#define VQ_D    768
#define VQ_D4   192          // float4s per row
#define VQ_ROWS 16           // rows per block
#define VQ_NBLK (VQ_BS / VQ_ROWS)   // 4096 blocks

// Deterministic per-block partial sums (no atomics, graph-safe, allocation-free).
__device__ float g_vq_partials[VQ_NBLK];

__global__ __launch_bounds__(VQ_D4) void vq_main_kernel(
    const float4* __restrict__ in,
    const int* __restrict__ cat,
    const float4* __restrict__ cb,
    float4* __restrict__ out)
{
    const int t    = threadIdx.x;             // 0..191 = column (float4)
    const int base = blockIdx.x * VQ_ROWS;

    // Hoist the index gather: one 64B read per 48KB of payload; kills the
    // per-row cat->cb serial dependency in the hot loop.
    __shared__ int scat[VQ_ROWS];
    if (t < VQ_ROWS) scat[t] = cat[base + t] & 511;   // mask = no-op on valid data
    __syncthreads();

    float s = 0.0f;

    #pragma unroll 4
    for (int r = 0; r < VQ_ROWS; r++) {
        const size_t ib = (size_t)(base + r) * VQ_D4 + t;
        float4 a = in[ib];
        float4 q = cb[(size_t)scat[r] * VQ_D4 + t];
        out[ib] = q;
        float dx = q.x - a.x;
        float dy = q.y - a.y;
        float dz = q.z - a.z;
        float dw = q.w - a.w;
        s += dx*dx + dy*dy + dz*dz + dw*dw;
    }

    // block reduction: 6 warps of 32
    #pragma unroll
    for (int o = 16; o > 0; o >>= 1)
        s += __shfl_down_sync(0xffffffffu, s, o);

    __shared__ float ws[6];
    if ((t & 31) == 0) ws[t >> 5] = s;
    __syncthreads();

    if (t == 0)
        g_vq_partials[blockIdx.x] = ws[0] + ws[1] + ws[2] + ws[3] + ws[4] + ws[5];
}

__global__ __launch_bounds__(1024) void vq_finalize_kernel(float* __restrict__ out,
                                                           int write_loss)
{
    const int t = threadIdx.x;
    double s = 0.0;
    // 4096 / 1024 = 4 values per thread, deterministic order
    #pragma unroll
    for (int i = 0; i < VQ_NBLK / 1024; i++)
        s += (double)g_vq_partials[t + i * 1024];

    #pragma unroll
    for (int o = 16; o > 0; o >>= 1)
        s += __shfl_down_sync(0xffffffffu, s, o);

    __shared__ double ws[32];
    if ((t & 31) == 0) ws[t >> 5] = s;
    __syncthreads();

    if (t < 32) {
        double v = ws[t];
        #pragma unroll
        for (int o = 16; o > 0; o >>= 1)
            v += __shfl_down_sync(0xffffffffu, v, o);
        if (t == 0 && write_loss) {
            const double inv_n = 1.0 / ((double)VQ_BS * (double)VQ_D);
            // loss = (CODEBOOK_COST + COMMITMENT_COST) * mse = 1.25 * mse
            out[(size_t)VQ_BS * VQ_D] = (float)(1.25 * v * inv_n);
        }
    }
}

extern "C" void kernel_launch(void* const* d_in, const int* in_sizes, int n_in,
                              void* d_out, int out_size)
{
    const float4* in  = (const float4*)d_in[0];
    const int*    cat = (const int*)d_in[1];
    const float4* cb  = (const float4*)d_in[2];
    float*        out = (float*)d_out;

    vq_main_kernel<<<VQ_NBLK, VQ_D4>>>(in, cat, cb, (float4*)out);

    const int write_loss = (out_size > VQ_BS * VQ_D) ? 1 : 0;
    vq_finalize_kernel<<<1, 1024>>>(out, write_loss);
}